// round 5
// baseline (speedup 1.0000x reference)
#include <cuda_runtime.h>
#include <cuda_bf16.h>
#include <math.h>

#define NB   8
#define CCH  256
#define HH   128
#define WW   128
#define HWSZ 16384
#define QKD  64

typedef unsigned int u32;
typedef __nv_bfloat16 bf16;

// ---------------- scratch ----------------
__device__ __align__(16) bf16 g_Wb[384 * CCH];          // [Wq;Wk;Wv] bf16
__device__ float g_psum[(size_t)NB * CCH * HH];
__device__ float g_pmax[(size_t)NB * CCH * HH];
__device__ float g_avg[NB * CCH];
__device__ float g_mx [NB * CCH];
__device__ float g_gate[NB * CCH];

// ---------------- helpers ----------------
__device__ __forceinline__ u32 smem_u32(const void* p) {
    u32 a;
    asm("{.reg .u64 t; cvta.to.shared.u64 t, %1; cvt.u32.u64 %0, t;}"
        : "=r"(a) : "l"(p));
    return a;
}
__device__ __forceinline__ void ldsm4(u32* r, u32 a) {
    asm volatile("ldmatrix.sync.aligned.m8n8.x4.shared.b16 {%0,%1,%2,%3},[%4];"
        : "=r"(r[0]), "=r"(r[1]), "=r"(r[2]), "=r"(r[3]) : "r"(a));
}
__device__ __forceinline__ void ldsm4t(u32* r, u32 a) {
    asm volatile("ldmatrix.sync.aligned.m8n8.x4.trans.shared.b16 {%0,%1,%2,%3},[%4];"
        : "=r"(r[0]), "=r"(r[1]), "=r"(r[2]), "=r"(r[3]) : "r"(a));
}
__device__ __forceinline__ void mma_bf(float* d, const u32* a, const u32* b) {
    asm volatile(
        "mma.sync.aligned.m16n8k16.row.col.f32.bf16.bf16.f32 "
        "{%0,%1,%2,%3},{%4,%5,%6,%7},{%8,%9},{%0,%1,%2,%3};"
        : "+f"(d[0]), "+f"(d[1]), "+f"(d[2]), "+f"(d[3])
        : "r"(a[0]), "r"(a[1]), "r"(a[2]), "r"(a[3]), "r"(b[0]), "r"(b[1]));
}
__device__ __forceinline__ u32 packbf(float lo, float hi) {
    u32 r; asm("cvt.rn.bf16x2.f32 %0,%1,%2;" : "=r"(r) : "f"(hi), "f"(lo));
    return r;
}

// ---------------------------------------------------------------------------
__global__ void convert_w(const float* __restrict__ Wq,
                          const float* __restrict__ Wk,
                          const float* __restrict__ Wv)
{
    int i = blockIdx.x * 256 + threadIdx.x;
    float v;
    if (i < 64 * 256)       v = Wq[i];
    else if (i < 128 * 256) v = Wk[i - 64 * 256];
    else                    v = Wv[i - 128 * 256];
    g_Wb[i] = __float2bfloat16(v);
}

// ---------------------------------------------------------------------------
// smem layout (bytes):
//  [0, 69632)        xt bf16 [256][136]     / later S fp32 [128][130]
//  [69632, 104448)   qk bf16 [128][136]     / later att bf16 [128][136]
//  [104448, 174080)  v  bf16 [256][136]
//  [174080, 178176)  psum[128*4] + pmax[128*4] fp32
//  [178176, 178688)  inv fp32 [128]
// ---------------------------------------------------------------------------
#define XT_PITCH 136
#define S_PITCH  130
#define QP       136
#define SMEM_TOTAL 178688

// in-smem GEMM: dst[128][QP] (bf16) = W[128][256] @ xt[256][128]
// 16 warps: wm = w&3 (m0=wm*32, mf 0..1), wn = w>>2 (n0=wn*32).
// A fragments loaded DIRECTLY from global (L1/L2-hot W).
__device__ __forceinline__ void gemm_wx(const bf16* __restrict__ Wbase,
                                        const bf16* xt, bf16* dst,
                                        int l, int m0, int n0)
{
    int g2 = l >> 2, tq2 = l & 3;

    float acc[2][4][4];
#pragma unroll
    for (int a = 0; a < 2; a++)
#pragma unroll
        for (int b = 0; b < 4; b++)
#pragma unroll
            for (int c = 0; c < 4; c++) acc[a][b][c] = 0.f;

#pragma unroll
    for (int kk = 0; kk < 256; kk += 16) {
        u32 a[2][4], b[4][2];
#pragma unroll
        for (int mf = 0; mf < 2; mf++) {
            const bf16* Ab = Wbase + (size_t)(m0 + mf * 16) * 256 + kk;
            a[mf][0] = *(const u32*)(Ab + (size_t)g2 * 256 + tq2 * 2);
            a[mf][1] = *(const u32*)(Ab + (size_t)(g2 + 8) * 256 + tq2 * 2);
            a[mf][2] = *(const u32*)(Ab + (size_t)g2 * 256 + tq2 * 2 + 8);
            a[mf][3] = *(const u32*)(Ab + (size_t)(g2 + 8) * 256 + tq2 * 2 + 8);
        }
        int br  = kk + ((l >> 3) & 1) * 8 + (l & 7);
        int bcl = (l >> 4) * 8;
#pragma unroll
        for (int bi = 0; bi < 2; bi++) {
            u32 r4[4];
            ldsm4t(r4, smem_u32(xt + br * XT_PITCH + n0 + bi * 16 + bcl));
            b[bi * 2][0] = r4[0]; b[bi * 2][1] = r4[1];
            b[bi * 2 + 1][0] = r4[2]; b[bi * 2 + 1][1] = r4[3];
        }
#pragma unroll
        for (int mf = 0; mf < 2; mf++)
#pragma unroll
            for (int nf = 0; nf < 4; nf++)
                mma_bf(acc[mf][nf], a[mf], b[nf]);
    }

    int g = l >> 2, tq = l & 3;
#pragma unroll
    for (int mf = 0; mf < 2; mf++)
#pragma unroll
        for (int nf = 0; nf < 4; nf++) {
            int col = n0 + nf * 8 + tq * 2;
            *(u32*)(dst + (m0 + mf * 16 + g) * QP + col)     = packbf(acc[mf][nf][0], acc[mf][nf][1]);
            *(u32*)(dst + (m0 + mf * 16 + g + 8) * QP + col) = packbf(acc[mf][nf][2], acc[mf][nf][3]);
        }
}

__global__ __launch_bounds__(512, 1) void fused_attn(const float* __restrict__ x,
                                                     float* __restrict__ out)
{
    extern __shared__ char smc[];
    bf16*  xt    = (bf16*)smc;
    float* S_s   = (float*)smc;
    bf16*  qk_s  = (bf16*)(smc + 69632);
    bf16*  att_s = qk_s;
    bf16*  v_s   = (bf16*)(smc + 104448);
    float* psum  = (float*)(smc + 174080);
    float* pmax  = psum + 512;
    float* inv_s = (float*)(smc + 178176);

    int nh = blockIdx.x, n = nh >> 7, h = nh & 127;
    int t = threadIdx.x, l = t & 31, w = t >> 5;
    int m0 = (w & 3) * 32, n0 = (w >> 2) * 32;

    // ---- load x tile (fp32 -> bf16 in-register) ----
    for (int e = t; e < 8192; e += 512) {
        int c = e >> 5, i4 = (e & 31) << 2;
        float4 v4 = *(const float4*)(x + ((size_t)(n * CCH + c) * HH + h) * WW + i4);
        uint2 o;
        o.x = packbf(v4.x, v4.y);
        o.y = packbf(v4.z, v4.w);
        *(uint2*)(xt + c * XT_PITCH + i4) = o;
    }
    __syncthreads();

    // ---- projections (no intra-GEMM syncs; disjoint outputs) ----
    gemm_wx(g_Wb,             xt, qk_s,           l, m0, n0);
    gemm_wx(g_Wb + 128 * 256, xt, v_s,            l, m0, n0);
    gemm_wx(g_Wb + 256 * 256, xt, v_s + 128 * QP, l, m0, n0);
    __syncthreads();

    // ---- logits: S[i][j] = sum_d q[d][i] k[d][j] ----
    {
        float acc[2][4][4];
#pragma unroll
        for (int a = 0; a < 2; a++)
#pragma unroll
            for (int b = 0; b < 4; b++)
#pragma unroll
                for (int c = 0; c < 4; c++) acc[a][b][c] = 0.f;

        const bf16* k_s = qk_s + 64 * QP;
#pragma unroll
        for (int ks = 0; ks < 4; ks++) {
            int k0 = ks * 16;
            u32 a[2][4], b[4][2];
            int ar  = k0 + ((l >> 4) << 3) + (l & 7);
            int acl = ((l >> 3) & 1) * 8;
#pragma unroll
            for (int mf = 0; mf < 2; mf++)
                ldsm4t(a[mf], smem_u32(qk_s + ar * QP + m0 + mf * 16 + acl));
            int br  = k0 + ((l >> 3) & 1) * 8 + (l & 7);
            int bcl = (l >> 4) * 8;
#pragma unroll
            for (int bi = 0; bi < 2; bi++) {
                u32 r4[4];
                ldsm4t(r4, smem_u32(k_s + br * QP + n0 + bi * 16 + bcl));
                b[bi * 2][0] = r4[0]; b[bi * 2][1] = r4[1];
                b[bi * 2 + 1][0] = r4[2]; b[bi * 2 + 1][1] = r4[3];
            }
#pragma unroll
            for (int mf = 0; mf < 2; mf++)
#pragma unroll
                for (int nf = 0; nf < 4; nf++)
                    mma_bf(acc[mf][nf], a[mf], b[nf]);
        }
        __syncthreads();   // qk reads done before S (xt region already free)
        int g = l >> 2, tq = l & 3;
#pragma unroll
        for (int mf = 0; mf < 2; mf++)
#pragma unroll
            for (int nf = 0; nf < 4; nf++) {
                int i = m0 + mf * 16 + g, j = n0 + nf * 8 + tq * 2;
                *(float2*)(S_s + i * S_PITCH + j)       = make_float2(acc[mf][nf][0], acc[mf][nf][1]);
                *(float2*)(S_s + (i + 8) * S_PITCH + j) = make_float2(acc[mf][nf][2], acc[mf][nf][3]);
            }
    }
    __syncthreads();

    // ---- softmax over j per row i; 4 threads per row ----
    {
        int i = t >> 2, q4 = t & 3;
        const float* Sr = S_s + i * S_PITCH;
        float m = -1e30f;
#pragma unroll 8
        for (int jj = 0; jj < 32; jj++) m = fmaxf(m, Sr[4 * jj + q4]);
        m = fmaxf(m, __shfl_xor_sync(0xffffffffu, m, 1));
        m = fmaxf(m, __shfl_xor_sync(0xffffffffu, m, 2));
        float s = 0.f;
        bf16* ar = att_s + i * QP;
#pragma unroll 8
        for (int jj = 0; jj < 32; jj++) {
            int j = 4 * jj + q4;
            float e = __expf(Sr[j] - m);
            s += e;
            ar[j] = __float2bfloat16(e);
        }
        s += __shfl_xor_sync(0xffffffffu, s, 1);
        s += __shfl_xor_sync(0xffffffffu, s, 2);
        if (q4 == 0) inv_s[i] = 1.f / s;
    }
    __syncthreads();

    // ---- att . V : out[c][i], 2 chunks of 128 channels ----
    int wg = w >> 2;
    for (int cc = 0; cc < 2; cc++) {
        const bf16* vc = v_s + (size_t)cc * 128 * QP;

        float acc[2][4][4];
#pragma unroll
        for (int a = 0; a < 2; a++)
#pragma unroll
            for (int b = 0; b < 4; b++)
#pragma unroll
                for (int c = 0; c < 4; c++) acc[a][b][c] = 0.f;

#pragma unroll
        for (int ks = 0; ks < 8; ks++) {
            int k0 = ks * 16;
            u32 a[2][4], b[4][2];
            int ar  = ((l >> 3) & 1) * 8 + (l & 7);
            int acl = k0 + (l >> 4) * 8;
#pragma unroll
            for (int mf = 0; mf < 2; mf++)
                ldsm4(a[mf], smem_u32(vc + (m0 + mf * 16 + ar) * QP + acl));
            int brr = (l >> 4) * 8 + (l & 7);
            int bcl = k0 + ((l >> 3) & 1) * 8;
#pragma unroll
            for (int bi = 0; bi < 2; bi++) {
                u32 r4[4];
                ldsm4(r4, smem_u32(att_s + (n0 + bi * 16 + brr) * QP + bcl));
                b[bi * 2][0] = r4[0]; b[bi * 2][1] = r4[1];
                b[bi * 2 + 1][0] = r4[2]; b[bi * 2 + 1][1] = r4[3];
            }
#pragma unroll
            for (int mf = 0; mf < 2; mf++)
#pragma unroll
                for (int nf = 0; nf < 4; nf++)
                    mma_bf(acc[mf][nf], a[mf], b[nf]);
        }

        int g = l >> 2, tq = l & 3;
#pragma unroll
        for (int mf = 0; mf < 2; mf++) {
            float rs0 = 0.f, rs1 = 0.f, rm0 = -1e30f, rm1 = -1e30f;
#pragma unroll
            for (int nf = 0; nf < 4; nf++) {
                int i = n0 + nf * 8 + tq * 2;
                float2 iv = *(float2*)(inv_s + i);
                int c = m0 + mf * 16 + g;
                float o0 = acc[mf][nf][0] * iv.x;
                float o1 = acc[mf][nf][1] * iv.y;
                float o2 = acc[mf][nf][2] * iv.x;
                float o3 = acc[mf][nf][3] * iv.y;
                size_t b0 = (((size_t)n * CCH + cc * 128 + c) * HH + h) * (size_t)WW + i;
                size_t b1 = (((size_t)n * CCH + cc * 128 + c + 8) * HH + h) * (size_t)WW + i;
                *(float2*)(out + b0) = make_float2(o0, o1);
                *(float2*)(out + b1) = make_float2(o2, o3);
                rs0 += o0 + o1; rm0 = fmaxf(rm0, fmaxf(o0, o1));
                rs1 += o2 + o3; rm1 = fmaxf(rm1, fmaxf(o2, o3));
            }
#pragma unroll
            for (int off = 1; off < 4; off <<= 1) {
                rs0 += __shfl_xor_sync(0xffffffffu, rs0, off);
                rs1 += __shfl_xor_sync(0xffffffffu, rs1, off);
                rm0 = fmaxf(rm0, __shfl_xor_sync(0xffffffffu, rm0, off));
                rm1 = fmaxf(rm1, __shfl_xor_sync(0xffffffffu, rm1, off));
            }
            if (tq == 0) {
                int c128 = m0 + mf * 16 + g;
                psum[c128 * 4 + wg]       = rs0;
                psum[(c128 + 8) * 4 + wg] = rs1;
                pmax[c128 * 4 + wg]       = rm0;
                pmax[(c128 + 8) * 4 + wg] = rm1;
            }
        }
        __syncthreads();
        if (t < 128) {
            float s = psum[t * 4] + psum[t * 4 + 1] + psum[t * 4 + 2] + psum[t * 4 + 3];
            float m = fmaxf(fmaxf(pmax[t * 4], pmax[t * 4 + 1]),
                            fmaxf(pmax[t * 4 + 2], pmax[t * 4 + 3]));
            size_t nc = (size_t)n * CCH + cc * 128 + t;
            g_psum[nc * HH + h] = s;
            g_pmax[nc * HH + h] = m;
        }
        __syncthreads();
    }
}

// ---------------------------------------------------------------------------
__global__ void reduce2()
{
    __shared__ float ss[4], sm[4];
    int nc = blockIdx.x, t = threadIdx.x;
    float s = g_psum[(size_t)nc * HH + t];
    float m = g_pmax[(size_t)nc * HH + t];
#pragma unroll
    for (int o = 16; o > 0; o >>= 1) {
        s += __shfl_xor_sync(0xffffffffu, s, o);
        m = fmaxf(m, __shfl_xor_sync(0xffffffffu, m, o));
    }
    if ((t & 31) == 0) { ss[t >> 5] = s; sm[t >> 5] = m; }
    __syncthreads();
    if (t == 0) {
        g_avg[nc] = (ss[0] + ss[1] + ss[2] + ss[3]) * (1.f / HWSZ);
        g_mx[nc]  = fmaxf(fmaxf(sm[0], sm[1]), fmaxf(sm[2], sm[3]));
    }
}

// ---------------------------------------------------------------------------
// gate: 512 threads. Stage1: 256 dots of len 256 split 2-way.
// Stage2: 2048 outputs, 4 per thread.
// ---------------------------------------------------------------------------
__global__ void gate_k(const float* __restrict__ W1, const float* __restrict__ W2)
{
    __shared__ float h1[NB][2][16];
    int t = threadIdx.x;
    {
        int dot = t >> 1, half = t & 1;
        int n = dot >> 5, rem = dot & 31, path = rem >> 4, r = rem & 15;
        const float* z = (path == 0 ? g_avg : g_mx) + n * CCH;
        const float* wr = W1 + r * CCH + half * 128;
        const float* zz = z + half * 128;
        float s = 0.f;
#pragma unroll 4
        for (int c = 0; c < 128; c++) s += wr[c] * zz[c];
        s += __shfl_xor_sync(0xffffffffu, s, 1);
        if (half == 0) h1[n][path][r] = fmaxf(s, 0.f);
    }
    __syncthreads();
#pragma unroll
    for (int o = t; o < NB * CCH; o += 512) {
        int n = o >> 8, c = o & 255;
        float g = 0.f;
#pragma unroll
        for (int r = 0; r < 16; r++)
            g += W2[c * 16 + r] * (h1[n][0][r] + h1[n][1][r]);
        g_gate[o] = 1.f / (1.f + __expf(-g));
    }
}

__global__ void final_k(const float* __restrict__ x,
                        const float* __restrict__ gama,
                        float* __restrict__ o)
{
    size_t idx = (size_t)blockIdx.x * blockDim.x + threadIdx.x;
    float g = gama[0];
    float4 ov = ((const float4*)o)[idx];
    float4 xv = ((const float4*)x)[idx];
    float gt = g * g_gate[idx >> 12];
    float4 r;
    r.x = gt * ov.x + xv.x;
    r.y = gt * ov.y + xv.y;
    r.z = gt * ov.z + xv.z;
    r.w = gt * ov.w + xv.w;
    ((float4*)o)[idx] = r;
}

// ---------------------------------------------------------------------------
extern "C" void kernel_launch(void* const* d_in, const int* in_sizes, int n_in,
                              void* d_out, int out_size)
{
    const float* x    = (const float*)d_in[0];
    const float* Wq   = (const float*)d_in[1];
    const float* Wk   = (const float*)d_in[2];
    const float* Wv   = (const float*)d_in[3];
    const float* W1   = (const float*)d_in[4];
    const float* W2   = (const float*)d_in[5];
    const float* gama = (const float*)d_in[6];
    float* out = (float*)d_out;

    cudaFuncSetAttribute(fused_attn, cudaFuncAttributeMaxDynamicSharedMemorySize, SMEM_TOTAL);

    convert_w<<<384, 256>>>(Wq, Wk, Wv);
    fused_attn<<<NB * HH, 512, SMEM_TOTAL>>>(x, out);
    reduce2<<<NB * CCH, 128>>>();
    gate_k<<<1, 512>>>(W1, W2);
    final_k<<<(NB * CCH * HWSZ) / 1024, 256>>>(x, gama, out);
}

// round 7
// speedup vs baseline: 1.7559x; 1.7559x over previous
#include <cuda_runtime.h>
#include <cuda_bf16.h>
#include <math.h>

#define NB   8
#define CCH  256
#define HH   128
#define WW   128
#define HWSZ 16384
#define QKD  64

typedef unsigned int u32;
typedef __nv_bfloat16 bf16;

// ---------------- scratch ----------------
// W in mma-fragment layout: [24 m-tiles][16 k-tiles][32 lanes] x uint4
__device__ uint4 g_Wf[24 * 16 * 32];
__device__ float g_psum[(size_t)NB * CCH * HH];
__device__ float g_pmax[(size_t)NB * CCH * HH];
__device__ float g_gate[NB * CCH];

// ---------------- helpers ----------------
__device__ __forceinline__ u32 smem_u32(const void* p) {
    u32 a;
    asm("{.reg .u64 t; cvta.to.shared.u64 t, %1; cvt.u32.u64 %0, t;}"
        : "=r"(a) : "l"(p));
    return a;
}
__device__ __forceinline__ void ldsm4(u32* r, u32 a) {
    asm volatile("ldmatrix.sync.aligned.m8n8.x4.shared.b16 {%0,%1,%2,%3},[%4];"
        : "=r"(r[0]), "=r"(r[1]), "=r"(r[2]), "=r"(r[3]) : "r"(a));
}
__device__ __forceinline__ void ldsm4t(u32* r, u32 a) {
    asm volatile("ldmatrix.sync.aligned.m8n8.x4.trans.shared.b16 {%0,%1,%2,%3},[%4];"
        : "=r"(r[0]), "=r"(r[1]), "=r"(r[2]), "=r"(r[3]) : "r"(a));
}
__device__ __forceinline__ void mma_bf(float* d, const u32* a, const u32* b) {
    asm volatile(
        "mma.sync.aligned.m16n8k16.row.col.f32.bf16.bf16.f32 "
        "{%0,%1,%2,%3},{%4,%5,%6,%7},{%8,%9},{%0,%1,%2,%3};"
        : "+f"(d[0]), "+f"(d[1]), "+f"(d[2]), "+f"(d[3])
        : "r"(a[0]), "r"(a[1]), "r"(a[2]), "r"(a[3]), "r"(b[0]), "r"(b[1]));
}
__device__ __forceinline__ u32 packbf(float lo, float hi) {
    u32 r; asm("cvt.rn.bf16x2.f32 %0,%1,%2;" : "=r"(r) : "f"(hi), "f"(lo));
    return r;
}

// ---------------------------------------------------------------------------
// convert W -> fragment layout. One thread per (m-tile, k-tile, lane) uint4.
// Fragment mapping (verified in R5): for tile (mt,kt), lane l (g2=l>>2, tq2=l&3):
//   a0 = W[mt*16+g2   ][kt*16+tq2*2 .. +1]
//   a1 = W[mt*16+g2+8 ][kt*16+tq2*2 .. +1]
//   a2 = W[mt*16+g2   ][kt*16+tq2*2+8 .. +9]
//   a3 = W[mt*16+g2+8 ][kt*16+tq2*2+8 .. +9]
// ---------------------------------------------------------------------------
__global__ void convert_w(const float* __restrict__ Wq,
                          const float* __restrict__ Wk,
                          const float* __restrict__ Wv)
{
    int tid = blockIdx.x * 256 + threadIdx.x;   // 0..12287
    int mt  = tid >> 9;
    int rem = tid & 511;
    int kt  = rem >> 5;
    int l   = rem & 31;
    int g2 = l >> 2, tq2 = l & 3;
    int r0 = mt * 16 + g2;          // 0..383 (rows r0 and r0+8 share source)
    int c0 = kt * 16 + tq2 * 2;

    const float* S; int roff;
    if (r0 < 64)       { S = Wq; roff = r0; }
    else if (r0 < 128) { S = Wk; roff = r0 - 64; }
    else               { S = Wv; roff = r0 - 128; }
    const float* p0 = S + (size_t)roff * CCH;
    const float* p8 = p0 + 8 * CCH;

    uint4 o;
    o.x = packbf(p0[c0],     p0[c0 + 1]);
    o.y = packbf(p8[c0],     p8[c0 + 1]);
    o.z = packbf(p0[c0 + 8], p0[c0 + 9]);
    o.w = packbf(p8[c0 + 8], p8[c0 + 9]);
    g_Wf[tid] = o;
}

// ---------------------------------------------------------------------------
// smem layout (bytes) — identical to R4:
//  [0, 69632)        xt bf16 [256][136]     / later S fp32 [128][130]
//  [69632, 104448)   qk bf16 [128][136]     / later att bf16 [128][136]
//  [104448, 174080)  v  bf16 [256][136]
//  [174080, 178176)  psum[128*4] + pmax[128*4] fp32
//  [178176, 178688)  inv fp32 [128]
// ---------------------------------------------------------------------------
#define XT_PITCH 136
#define S_PITCH  130
#define QP       136
#define SMEM_TOTAL 178688

// dst[128][QP] (bf16) = W-block(wt0) @ xt[256][128]; A frags direct from g_Wf.
// 8 warps: m0 = (w&1)*64 (mf 0..3), n0 = (w>>1)*32. Zero syncs inside.
__device__ __forceinline__ void gemm_wx(int wt0, const bf16* xt, bf16* dst,
                                        int l, int m0, int n0)
{
    float acc[4][4][4];
#pragma unroll
    for (int a = 0; a < 4; a++)
#pragma unroll
        for (int b = 0; b < 4; b++)
#pragma unroll
            for (int c = 0; c < 4; c++) acc[a][b][c] = 0.f;

    int mt0 = wt0 + (m0 >> 4);
#pragma unroll
    for (int kt = 0; kt < 16; kt++) {
        u32 a[4][4], b[4][2];
#pragma unroll
        for (int mf = 0; mf < 4; mf++) {
            uint4 av = g_Wf[(size_t)((mt0 + mf) * 16 + kt) * 32 + l];
            a[mf][0] = av.x; a[mf][1] = av.y; a[mf][2] = av.z; a[mf][3] = av.w;
        }
        int kk = kt * 16;
        int br  = kk + ((l >> 3) & 1) * 8 + (l & 7);
        int bcl = (l >> 4) * 8;
#pragma unroll
        for (int bi = 0; bi < 2; bi++) {
            u32 r4[4];
            ldsm4t(r4, smem_u32(xt + br * XT_PITCH + n0 + bi * 16 + bcl));
            b[bi * 2][0] = r4[0]; b[bi * 2][1] = r4[1];
            b[bi * 2 + 1][0] = r4[2]; b[bi * 2 + 1][1] = r4[3];
        }
#pragma unroll
        for (int mf = 0; mf < 4; mf++)
#pragma unroll
            for (int nf = 0; nf < 4; nf++)
                mma_bf(acc[mf][nf], a[mf], b[nf]);
    }

    int g = l >> 2, tq = l & 3;
#pragma unroll
    for (int mf = 0; mf < 4; mf++)
#pragma unroll
        for (int nf = 0; nf < 4; nf++) {
            int col = n0 + nf * 8 + tq * 2;
            *(u32*)(dst + (m0 + mf * 16 + g) * QP + col)     = packbf(acc[mf][nf][0], acc[mf][nf][1]);
            *(u32*)(dst + (m0 + mf * 16 + g + 8) * QP + col) = packbf(acc[mf][nf][2], acc[mf][nf][3]);
        }
}

__global__ __launch_bounds__(256, 1) void fused_attn(const float* __restrict__ x,
                                                     float* __restrict__ out)
{
    extern __shared__ char smc[];
    bf16*  xt    = (bf16*)smc;
    float* S_s   = (float*)smc;
    bf16*  qk_s  = (bf16*)(smc + 69632);
    bf16*  att_s = qk_s;
    bf16*  v_s   = (bf16*)(smc + 104448);
    float* psum  = (float*)(smc + 174080);
    float* pmax  = psum + 512;
    float* inv_s = (float*)(smc + 178176);

    int nh = blockIdx.x, n = nh >> 7, h = nh & 127;
    int t = threadIdx.x, l = t & 31, w = t >> 5;
    int m0 = (w & 1) * 64, n0 = (w >> 1) * 32;

    // ---- load x tile (fp32 -> bf16 in-register) ----
    for (int e = t; e < 8192; e += 256) {
        int c = e >> 5, i4 = (e & 31) << 2;
        float4 v4 = *(const float4*)(x + ((size_t)(n * CCH + c) * HH + h) * WW + i4);
        uint2 o;
        o.x = packbf(v4.x, v4.y);
        o.y = packbf(v4.z, v4.w);
        *(uint2*)(xt + c * XT_PITCH + i4) = o;
    }
    __syncthreads();

    // ---- projections (A frags from global, zero intra-GEMM syncs) ----
    gemm_wx(0,  xt, qk_s,           l, m0, n0);
    gemm_wx(8,  xt, v_s,            l, m0, n0);
    gemm_wx(16, xt, v_s + 128 * QP, l, m0, n0);
    __syncthreads();

    // ---- logits: S[i][j] = sum_d q[d][i] k[d][j] ----
    {
        float acc[4][4][4];
#pragma unroll
        for (int a = 0; a < 4; a++)
#pragma unroll
            for (int b = 0; b < 4; b++)
#pragma unroll
                for (int c = 0; c < 4; c++) acc[a][b][c] = 0.f;

        const bf16* k_s = qk_s + 64 * QP;
#pragma unroll
        for (int ks = 0; ks < 4; ks++) {
            int k0 = ks * 16;
            u32 a[4][4], b[4][2];
            int ar  = k0 + ((l >> 4) << 3) + (l & 7);
            int acl = ((l >> 3) & 1) * 8;
#pragma unroll
            for (int mf = 0; mf < 4; mf++)
                ldsm4t(a[mf], smem_u32(qk_s + ar * QP + m0 + mf * 16 + acl));
            int br  = k0 + ((l >> 3) & 1) * 8 + (l & 7);
            int bcl = (l >> 4) * 8;
#pragma unroll
            for (int bi = 0; bi < 2; bi++) {
                u32 r4[4];
                ldsm4t(r4, smem_u32(k_s + br * QP + n0 + bi * 16 + bcl));
                b[bi * 2][0] = r4[0]; b[bi * 2][1] = r4[1];
                b[bi * 2 + 1][0] = r4[2]; b[bi * 2 + 1][1] = r4[3];
            }
#pragma unroll
            for (int mf = 0; mf < 4; mf++)
#pragma unroll
                for (int nf = 0; nf < 4; nf++)
                    mma_bf(acc[mf][nf], a[mf], b[nf]);
        }
        __syncthreads();   // qk reads done before S overwrites xt region
        int g = l >> 2, tq = l & 3;
#pragma unroll
        for (int mf = 0; mf < 4; mf++)
#pragma unroll
            for (int nf = 0; nf < 4; nf++) {
                int i = m0 + mf * 16 + g, j = n0 + nf * 8 + tq * 2;
                *(float2*)(S_s + i * S_PITCH + j)       = make_float2(acc[mf][nf][0], acc[mf][nf][1]);
                *(float2*)(S_s + (i + 8) * S_PITCH + j) = make_float2(acc[mf][nf][2], acc[mf][nf][3]);
            }
    }
    __syncthreads();

    // ---- softmax over j per row i ----
    {
        int i = t >> 1, hf = t & 1;
        const float* Sr = S_s + i * S_PITCH;
        float m = -1e30f;
#pragma unroll 8
        for (int jj = 0; jj < 64; jj++) m = fmaxf(m, Sr[2 * jj + hf]);
        m = fmaxf(m, __shfl_xor_sync(0xffffffffu, m, 1));
        float s = 0.f;
        bf16* ar = att_s + i * QP;
#pragma unroll 8
        for (int jj = 0; jj < 64; jj++) {
            int j = 2 * jj + hf;
            float e = __expf(Sr[j] - m);
            s += e;
            ar[j] = __float2bfloat16(e);
        }
        s += __shfl_xor_sync(0xffffffffu, s, 1);
        if (hf == 0) inv_s[i] = 1.f / s;
    }
    __syncthreads();

    // ---- att . V : out[c][i], 2 chunks of 128 channels ----
    int wg = w >> 1;
    for (int cc = 0; cc < 2; cc++) {
        const bf16* vc = v_s + (size_t)cc * 128 * QP;

        float acc[4][4][4];
#pragma unroll
        for (int a = 0; a < 4; a++)
#pragma unroll
            for (int b = 0; b < 4; b++)
#pragma unroll
                for (int c = 0; c < 4; c++) acc[a][b][c] = 0.f;

#pragma unroll
        for (int ks = 0; ks < 8; ks++) {
            int k0 = ks * 16;
            u32 a[4][4], b[4][2];
            int ar  = ((l >> 3) & 1) * 8 + (l & 7);
            int acl = k0 + (l >> 4) * 8;
#pragma unroll
            for (int mf = 0; mf < 4; mf++)
                ldsm4(a[mf], smem_u32(vc + (m0 + mf * 16 + ar) * QP + acl));
            int brr = (l >> 4) * 8 + (l & 7);
            int bcl = k0 + ((l >> 3) & 1) * 8;
#pragma unroll
            for (int bi = 0; bi < 2; bi++) {
                u32 r4[4];
                ldsm4(r4, smem_u32(att_s + (n0 + bi * 16 + brr) * QP + bcl));
                b[bi * 2][0] = r4[0]; b[bi * 2][1] = r4[1];
                b[bi * 2 + 1][0] = r4[2]; b[bi * 2 + 1][1] = r4[3];
            }
#pragma unroll
            for (int mf = 0; mf < 4; mf++)
#pragma unroll
                for (int nf = 0; nf < 4; nf++)
                    mma_bf(acc[mf][nf], a[mf], b[nf]);
        }

        int g = l >> 2, tq = l & 3;
#pragma unroll
        for (int mf = 0; mf < 4; mf++) {
            float rs0 = 0.f, rs1 = 0.f, rm0 = -1e30f, rm1 = -1e30f;
#pragma unroll
            for (int nf = 0; nf < 4; nf++) {
                int i = n0 + nf * 8 + tq * 2;
                float2 iv = *(float2*)(inv_s + i);
                int c = m0 + mf * 16 + g;
                float o0 = acc[mf][nf][0] * iv.x;
                float o1 = acc[mf][nf][1] * iv.y;
                float o2 = acc[mf][nf][2] * iv.x;
                float o3 = acc[mf][nf][3] * iv.y;
                size_t b0 = (((size_t)n * CCH + cc * 128 + c) * HH + h) * (size_t)WW + i;
                size_t b1 = (((size_t)n * CCH + cc * 128 + c + 8) * HH + h) * (size_t)WW + i;
                *(float2*)(out + b0) = make_float2(o0, o1);
                *(float2*)(out + b1) = make_float2(o2, o3);
                rs0 += o0 + o1; rm0 = fmaxf(rm0, fmaxf(o0, o1));
                rs1 += o2 + o3; rm1 = fmaxf(rm1, fmaxf(o2, o3));
            }
#pragma unroll
            for (int off = 1; off < 4; off <<= 1) {
                rs0 += __shfl_xor_sync(0xffffffffu, rs0, off);
                rs1 += __shfl_xor_sync(0xffffffffu, rs1, off);
                rm0 = fmaxf(rm0, __shfl_xor_sync(0xffffffffu, rm0, off));
                rm1 = fmaxf(rm1, __shfl_xor_sync(0xffffffffu, rm1, off));
            }
            if (tq == 0) {
                int c128 = m0 + mf * 16 + g;
                psum[c128 * 4 + wg]       = rs0;
                psum[(c128 + 8) * 4 + wg] = rs1;
                pmax[c128 * 4 + wg]       = rm0;
                pmax[(c128 + 8) * 4 + wg] = rm1;
            }
        }
        __syncthreads();
        if (t < 128) {
            float s = psum[t * 4] + psum[t * 4 + 1] + psum[t * 4 + 2] + psum[t * 4 + 3];
            float m = fmaxf(fmaxf(pmax[t * 4], pmax[t * 4 + 1]),
                            fmaxf(pmax[t * 4 + 2], pmax[t * 4 + 3]));
            size_t nc = (size_t)n * CCH + cc * 128 + t;
            g_psum[nc * HH + h] = s;
            g_pmax[nc * HH + h] = m;
        }
        __syncthreads();
    }
}

// ---------------------------------------------------------------------------
// merged reduce + SE gate: one block per n (8 blocks, 256 threads)
// ---------------------------------------------------------------------------
__global__ void gate2(const float* __restrict__ W1, const float* __restrict__ W2)
{
    __shared__ float avg[CCH], mx[CCH], h1[2][16];
    int n = blockIdx.x, t = threadIdx.x;

    {   // reduce over h for channel c = t
        const float4* ps = (const float4*)(g_psum + ((size_t)n * CCH + t) * HH);
        const float4* pm = (const float4*)(g_pmax + ((size_t)n * CCH + t) * HH);
        float s = 0.f, m = -1e30f;
#pragma unroll 8
        for (int q = 0; q < 32; q++) {
            float4 a = ps[q];
            s += a.x + a.y + a.z + a.w;
            float4 b = pm[q];
            m = fmaxf(m, fmaxf(fmaxf(b.x, b.y), fmaxf(b.z, b.w)));
        }
        avg[t] = s * (1.f / HWSZ);
        mx[t]  = m;
    }
    __syncthreads();

    {   // stage1: 32 dots of len 256, 8 threads each
        int dot = t >> 3, part = t & 7;
        int path = dot >> 4, r = dot & 15;
        const float* z  = path ? mx : avg;
        const float* wr = W1 + r * CCH + part * 32;
        float acc = 0.f;
#pragma unroll 8
        for (int c = 0; c < 32; c++) acc += wr[c] * z[part * 32 + c];
        acc += __shfl_xor_sync(0xffffffffu, acc, 1);
        acc += __shfl_xor_sync(0xffffffffu, acc, 2);
        acc += __shfl_xor_sync(0xffffffffu, acc, 4);
        if (part == 0 && t < 256) h1[path][r] = fmaxf(acc, 0.f);
    }
    __syncthreads();

    {   // stage2 + sigmoid
        float g = 0.f;
#pragma unroll
        for (int r = 0; r < 16; r++)
            g += W2[t * 16 + r] * (h1[0][r] + h1[1][r]);
        g_gate[n * CCH + t] = 1.f / (1.f + __expf(-g));
    }
}

__global__ void final_k(const float* __restrict__ x,
                        const float* __restrict__ gama,
                        float* __restrict__ o)
{
    size_t idx = (size_t)blockIdx.x * blockDim.x + threadIdx.x;
    float g = gama[0];
    float4 ov = ((const float4*)o)[idx];
    float4 xv = ((const float4*)x)[idx];
    float gt = g * g_gate[idx >> 12];
    float4 r;
    r.x = gt * ov.x + xv.x;
    r.y = gt * ov.y + xv.y;
    r.z = gt * ov.z + xv.z;
    r.w = gt * ov.w + xv.w;
    ((float4*)o)[idx] = r;
}

// ---------------------------------------------------------------------------
extern "C" void kernel_launch(void* const* d_in, const int* in_sizes, int n_in,
                              void* d_out, int out_size)
{
    const float* x    = (const float*)d_in[0];
    const float* Wq   = (const float*)d_in[1];
    const float* Wk   = (const float*)d_in[2];
    const float* Wv   = (const float*)d_in[3];
    const float* W1   = (const float*)d_in[4];
    const float* W2   = (const float*)d_in[5];
    const float* gama = (const float*)d_in[6];
    float* out = (float*)d_out;

    cudaFuncSetAttribute(fused_attn, cudaFuncAttributeMaxDynamicSharedMemorySize, SMEM_TOTAL);

    convert_w<<<48, 256>>>(Wq, Wk, Wv);
    fused_attn<<<NB * HH, 256, SMEM_TOTAL>>>(x, out);
    gate2<<<NB, 256>>>(W1, W2);
    final_k<<<(NB * CCH * HWSZ) / 1024, 256>>>(x, gama, out);
}